// round 2
// baseline (speedup 1.0000x reference)
#include <cuda_runtime.h>
#include <cuda_fp16.h>
#include <cstdint>

// D[b,o] = sum_ck A[b,ck] * W[o,ck]   — GEMM M=256, N=1024, K=16384, fp32 I/O.
// fp16 operands (converted on the fly), fp32 accumulate via mma.sync m16n8k16.
// Target is plain sm_100 (harness flag): no tcgen05/TMEM — legacy HMMA path.
#define B_DIM   256
#define N_DIM   1024
#define K_DIM   16384
#define TILE_M  128
#define TILE_N  128
#define TILE_K  32
#define SPLITK  8
#define K_PER_CTA (K_DIM / SPLITK)       // 2048
#define NITER   (K_PER_CTA / TILE_K)     // 64
#define NTHREADS 256

// Smem tile: 128 rows x 32 halfs, padded row stride 40 halfs (80 B) -> ldmatrix
// conflict-free (80*r mod 128 distinct for r=0..7).
#define ROW_HB   80                       // row stride in bytes
#define TILE_HB  (128 * ROW_HB)           // 10240 B per tile
#define STAGE_HB (2 * TILE_HB)            // A + B per stage
#define SMEM_BYTES (2 * STAGE_HB)         // double buffer = 40960 B

__device__ float g_part[SPLITK * B_DIM * N_DIM];

__device__ __forceinline__ uint32_t smem_u32(const void* p) {
    uint32_t a;
    asm("{ .reg .u64 t; cvta.to.shared.u64 t, %1; cvt.u32.u64 %0, t; }" : "=r"(a) : "l"(p));
    return a;
}

__device__ __forceinline__ void ldmx4(uint32_t* r, uint32_t addr) {
    asm volatile("ldmatrix.sync.aligned.m8n8.x4.shared.b16 {%0,%1,%2,%3}, [%4];"
                 : "=r"(r[0]), "=r"(r[1]), "=r"(r[2]), "=r"(r[3]) : "r"(addr));
}

__device__ __forceinline__ void mma16816(float* d, const uint32_t* a, const uint32_t* b) {
    asm volatile(
        "mma.sync.aligned.m16n8k16.row.col.f32.f16.f16.f32 "
        "{%0,%1,%2,%3}, {%4,%5,%6,%7}, {%8,%9}, {%0,%1,%2,%3};"
        : "+f"(d[0]), "+f"(d[1]), "+f"(d[2]), "+f"(d[3])
        : "r"(a[0]), "r"(a[1]), "r"(a[2]), "r"(a[3]), "r"(b[0]), "r"(b[1]));
}

__device__ __forceinline__ uint2 pack4h(float4 v) {
    __half2 lo = __floats2half2_rn(v.x, v.y);
    __half2 hi = __floats2half2_rn(v.z, v.w);
    uint2 r;
    r.x = *(uint32_t*)&lo;
    r.y = *(uint32_t*)&hi;
    return r;
}

__global__ void __launch_bounds__(NTHREADS, 1)
StreamingConv_gemm_kernel(const float* __restrict__ A, const float* __restrict__ W)
{
    __shared__ __align__(16) char smem[SMEM_BYTES];
    const uint32_t sb = smem_u32(smem);

    const int tid = threadIdx.x;
    const int lane = tid & 31;
    const int wid = tid >> 5;
    const int wm = wid >> 1;          // 0..3  -> 32-row band of M
    const int wn = wid & 1;           // 0..1  -> 64-col band of N

    const int m0 = blockIdx.y * TILE_M;
    const int n0 = blockIdx.x * TILE_N;
    const int sk = blockIdx.z;
    const size_t kbase = (size_t)sk * K_PER_CTA;

    // ---- gmem load mapping: 4 float4 for A + 4 for W per thread per iter ----
    const float* pa[4];
    const float* pb[4];
    uint32_t sts_off[4];
    #pragma unroll
    for (int i = 0; i < 4; i++) {
        const int idx = tid + NTHREADS * i;
        const int row = idx >> 3;     // 0..127
        const int c4  = idx & 7;      // float4 within the 32-float row
        pa[i] = A + (size_t)(m0 + row) * K_DIM + kbase + c4 * 4;
        pb[i] = W + (size_t)(n0 + row) * K_DIM + kbase + c4 * 4;
        sts_off[i] = (uint32_t)(row * ROW_HB + c4 * 8);   // 4 halfs = 8 B
    }

    // ---- ldmatrix per-lane tile offsets ----
    uint32_t a_off[2];
    #pragma unroll
    for (int mt = 0; mt < 2; mt++)
        a_off[mt] = (uint32_t)((wm * 32 + mt * 16 + (lane & 15)) * ROW_HB + (lane >> 4) * 16);
    uint32_t b_off[4];
    #pragma unroll
    for (int pj = 0; pj < 4; pj++)
        b_off[pj] = (uint32_t)((wn * 64 + (2 * pj + (lane >> 4)) * 8 + (lane & 7)) * ROW_HB
                               + ((lane >> 3) & 1) * 16);

    float acc[2][8][4];
    #pragma unroll
    for (int mt = 0; mt < 2; mt++)
        #pragma unroll
        for (int nt = 0; nt < 8; nt++)
            #pragma unroll
            for (int j = 0; j < 4; j++) acc[mt][nt][j] = 0.f;

    float4 ra[4], rb[4];

    // prologue: load + convert + store iter 0 into stage 0
    #pragma unroll
    for (int i = 0; i < 4; i++) { ra[i] = *(const float4*)pa[i]; rb[i] = *(const float4*)pb[i]; }
    #pragma unroll
    for (int i = 0; i < 4; i++) {
        *(uint2*)(smem + sts_off[i])           = pack4h(ra[i]);
        *(uint2*)(smem + TILE_HB + sts_off[i]) = pack4h(rb[i]);
    }
    __syncthreads();

    for (int it = 0; it < NITER; ++it) {
        const uint32_t cur = (uint32_t)(it & 1) * STAGE_HB;
        const uint32_t nxt = STAGE_HB - cur;

        // prefetch iter+1 into registers (overlaps with MMA below)
        if (it + 1 < NITER) {
            const size_t ko = (size_t)(it + 1) * TILE_K;
            #pragma unroll
            for (int i = 0; i < 4; i++) {
                ra[i] = *(const float4*)(pa[i] + ko);
                rb[i] = *(const float4*)(pb[i] + ko);
            }
        }

        // compute current tile
        const uint32_t baseA = sb + cur;
        const uint32_t baseB = sb + cur + TILE_HB;
        #pragma unroll
        for (int ks = 0; ks < 2; ks++) {
            uint32_t afr[2][4], bfr[4][4];
            #pragma unroll
            for (int mt = 0; mt < 2; mt++) ldmx4(afr[mt], baseA + a_off[mt] + ks * 32);
            #pragma unroll
            for (int pj = 0; pj < 4; pj++) ldmx4(bfr[pj], baseB + b_off[pj] + ks * 32);
            #pragma unroll
            for (int mt = 0; mt < 2; mt++)
                #pragma unroll
                for (int nt = 0; nt < 8; nt++) {
                    uint32_t bb[2] = { bfr[nt >> 1][(nt & 1) * 2], bfr[nt >> 1][(nt & 1) * 2 + 1] };
                    mma16816(acc[mt][nt], afr[mt], bb);
                }
        }

        // convert + store prefetched tile into the other stage
        if (it + 1 < NITER) {
            #pragma unroll
            for (int i = 0; i < 4; i++) {
                *(uint2*)(smem + nxt + sts_off[i])           = pack4h(ra[i]);
                *(uint2*)(smem + nxt + TILE_HB + sts_off[i]) = pack4h(rb[i]);
            }
        }
        __syncthreads();
    }

    // ---- epilogue: write split-K partials (deterministic; no atomics) ----
    float* base = &g_part[(size_t)sk * (B_DIM * N_DIM)];
    #pragma unroll
    for (int mt = 0; mt < 2; mt++) {
        const int row0 = m0 + wm * 32 + mt * 16 + (lane >> 2);
        #pragma unroll
        for (int nt = 0; nt < 8; nt++) {
            const int col = n0 + wn * 64 + nt * 8 + 2 * (lane & 3);
            *(float2*)&base[(size_t)row0 * N_DIM + col]       = make_float2(acc[mt][nt][0], acc[mt][nt][1]);
            *(float2*)&base[(size_t)(row0 + 8) * N_DIM + col] = make_float2(acc[mt][nt][2], acc[mt][nt][3]);
        }
    }
}

__global__ void StreamingConv_reduce_kernel(float* __restrict__ out)
{
    const int idx = blockIdx.x * blockDim.x + threadIdx.x;   // float4 index
    const float4* p = (const float4*)g_part;
    float4 acc = p[idx];
    #pragma unroll
    for (int i = 1; i < SPLITK; i++) {
        const float4 v = p[(size_t)i * (B_DIM * N_DIM / 4) + idx];
        acc.x += v.x; acc.y += v.y; acc.z += v.z; acc.w += v.w;
    }
    ((float4*)out)[idx] = acc;
}

extern "C" void kernel_launch(void* const* d_in, const int* in_sizes, int n_in,
                              void* d_out, int out_size)
{
    const float* A = (const float*)d_in[0];   // curr_input [256, 1024, 16]
    const float* W = (const float*)d_in[1];   // weight     [1024, 1024, 16]

    dim3 grid(N_DIM / TILE_N, B_DIM / TILE_M, SPLITK);   // (8, 2, 8) = 128 CTAs
    StreamingConv_gemm_kernel<<<grid, NTHREADS>>>(A, W);
    StreamingConv_reduce_kernel<<<(B_DIM * N_DIM / 4) / 256, 256>>>((float*)d_out);
}

// round 3
// speedup vs baseline: 1.1006x; 1.1006x over previous
#include <cuda_runtime.h>
#include <cuda_fp16.h>
#include <cstdint>

// D[b,o] = sum_ck A[b,ck] * W[o,ck] — GEMM M=256, N=1024, K=16384, fp32 I/O.
// fp16 operands (converted in registers), fp32 accumulate, mma.sync m16n8k16.
// 4-deep register staging pipeline hides DRAM latency; TILE_K=16.
#define B_DIM   256
#define N_DIM   1024
#define K_DIM   16384
#define TILE_M  128
#define TILE_N  128
#define TILE_K  16
#define SPLITK  8
#define K_PER_CTA (K_DIM / SPLITK)       // 2048
#define NITER   (K_PER_CTA / TILE_K)     // 128
#define DEPTH   4                        // register staging depth
#define NTHREADS 256

// Smem tile: 128 rows x 16 halfs (32 B), padded stride 48 B (16-aligned for
// ldmatrix; 48*r mod 128 covers 8 distinct 16B banks -> conflict-free LDSM).
#define ROW_HB   48
#define TILE_HB  (128 * ROW_HB)           // 6144 B
#define STAGE_HB (2 * TILE_HB)            // A + B per stage
#define SMEM_BYTES (2 * STAGE_HB)         // double buffer = 24576 B

__device__ float g_part[SPLITK * B_DIM * N_DIM];

__device__ __forceinline__ uint32_t smem_u32(const void* p) {
    uint32_t a;
    asm("{ .reg .u64 t; cvta.to.shared.u64 t, %1; cvt.u32.u64 %0, t; }" : "=r"(a) : "l"(p));
    return a;
}

__device__ __forceinline__ void ldmx4(uint32_t* r, uint32_t addr) {
    asm volatile("ldmatrix.sync.aligned.m8n8.x4.shared.b16 {%0,%1,%2,%3}, [%4];"
                 : "=r"(r[0]), "=r"(r[1]), "=r"(r[2]), "=r"(r[3]) : "r"(addr));
}

__device__ __forceinline__ void mma16816(float* d, const uint32_t* a, const uint32_t* b) {
    asm volatile(
        "mma.sync.aligned.m16n8k16.row.col.f32.f16.f16.f32 "
        "{%0,%1,%2,%3}, {%4,%5,%6,%7}, {%8,%9}, {%0,%1,%2,%3};"
        : "+f"(d[0]), "+f"(d[1]), "+f"(d[2]), "+f"(d[3])
        : "r"(a[0]), "r"(a[1]), "r"(a[2]), "r"(a[3]), "r"(b[0]), "r"(b[1]));
}

__device__ __forceinline__ uint2 pack4h(float4 v) {
    __half2 lo = __floats2half2_rn(v.x, v.y);
    __half2 hi = __floats2half2_rn(v.z, v.w);
    uint2 r;
    r.x = *(uint32_t*)&lo;
    r.y = *(uint32_t*)&hi;
    return r;
}

__global__ void __launch_bounds__(NTHREADS, 1)
StreamingConv_gemm_kernel(const float* __restrict__ A, const float* __restrict__ W)
{
    __shared__ __align__(16) char smem[SMEM_BYTES];
    const uint32_t sb = smem_u32(smem);

    const int tid = threadIdx.x;
    const int lane = tid & 31;
    const int wid = tid >> 5;
    const int wm = wid >> 1;          // 0..3 -> 32-row band of M
    const int wn = wid & 1;           // 0..1 -> 64-col band of N

    const int m0 = blockIdx.y * TILE_M;
    const int n0 = blockIdx.x * TILE_N;
    const int sk = blockIdx.z;
    const size_t kbase = (size_t)sk * K_PER_CTA;

    // ---- gmem load mapping: 2 float4 for A + 2 for W per thread per iter ----
    // tile = 128 rows x 4 float4; idx = tid + 256*i -> row = idx>>2, c4 = idx&3
    const float* pa[2];
    const float* pb[2];
    uint32_t sts_off[2];
    #pragma unroll
    for (int i = 0; i < 2; i++) {
        const int idx = tid + NTHREADS * i;
        const int row = idx >> 2;
        const int c4  = idx & 3;
        pa[i] = A + (size_t)(m0 + row) * K_DIM + kbase + c4 * 4;
        pb[i] = W + (size_t)(n0 + row) * K_DIM + kbase + c4 * 4;
        sts_off[i] = (uint32_t)(row * ROW_HB + c4 * 8);
    }

    // ---- ldmatrix per-lane tile offsets ----
    uint32_t a_off[2];
    #pragma unroll
    for (int mt = 0; mt < 2; mt++)
        a_off[mt] = (uint32_t)((wm * 32 + mt * 16 + (lane & 15)) * ROW_HB + (lane >> 4) * 16);
    uint32_t b_off[4];
    #pragma unroll
    for (int pj = 0; pj < 4; pj++)
        b_off[pj] = (uint32_t)((wn * 64 + (2 * pj + (lane >> 4)) * 8 + (lane & 7)) * ROW_HB
                               + ((lane >> 3) & 1) * 16);

    float acc[2][8][4];
    #pragma unroll
    for (int mt = 0; mt < 2; mt++)
        #pragma unroll
        for (int nt = 0; nt < 8; nt++)
            #pragma unroll
            for (int j = 0; j < 4; j++) acc[mt][nt][j] = 0.f;

    // ---- 4-deep register staging queue ----
    float4 qa[DEPTH][2], qb[DEPTH][2];

    // prologue: issue LDG for k0..k3, STS k0 into stage 0
    #pragma unroll
    for (int d = 0; d < DEPTH; d++) {
        const size_t ko = (size_t)d * TILE_K;
        #pragma unroll
        for (int i = 0; i < 2; i++) {
            qa[d][i] = *(const float4*)(pa[i] + ko);
            qb[d][i] = *(const float4*)(pb[i] + ko);
        }
    }
    #pragma unroll
    for (int i = 0; i < 2; i++) {
        *(uint2*)(smem + sts_off[i])           = pack4h(qa[0][i]);
        *(uint2*)(smem + TILE_HB + sts_off[i]) = pack4h(qb[0][i]);
    }
    __syncthreads();

    #pragma unroll 4
    for (int it = 0; it < NITER; ++it) {
        // issue LDG for k(it+4) into the slot freed by last iter's STS
        if (it + DEPTH < NITER) {
            const size_t ko = (size_t)(it + DEPTH) * TILE_K;
            const int d = it & (DEPTH - 1);
            #pragma unroll
            for (int i = 0; i < 2; i++) {
                qa[d][i] = *(const float4*)(pa[i] + ko);
                qb[d][i] = *(const float4*)(pb[i] + ko);
            }
        }

        // compute current tile from stage it&1
        const uint32_t baseA = sb + (uint32_t)(it & 1) * STAGE_HB;
        const uint32_t baseB = baseA + TILE_HB;
        {
            uint32_t afr[2][4], bfr[4][4];
            #pragma unroll
            for (int mt = 0; mt < 2; mt++) ldmx4(afr[mt], baseA + a_off[mt]);
            #pragma unroll
            for (int pj = 0; pj < 4; pj++) ldmx4(bfr[pj], baseB + b_off[pj]);
            #pragma unroll
            for (int mt = 0; mt < 2; mt++)
                #pragma unroll
                for (int nt = 0; nt < 8; nt++) {
                    uint32_t bb[2] = { bfr[nt >> 1][(nt & 1) * 2], bfr[nt >> 1][(nt & 1) * 2 + 1] };
                    mma16816(acc[mt][nt], afr[mt], bb);
                }
        }

        // store k(it+1) (loaded 3 iters ago -> latency fully covered)
        if (it + 1 < NITER) {
            const uint32_t nxt = (uint32_t)((it + 1) & 1) * STAGE_HB;
            const int d = (it + 1) & (DEPTH - 1);
            #pragma unroll
            for (int i = 0; i < 2; i++) {
                *(uint2*)(smem + nxt + sts_off[i])           = pack4h(qa[d][i]);
                *(uint2*)(smem + nxt + TILE_HB + sts_off[i]) = pack4h(qb[d][i]);
            }
        }
        __syncthreads();
    }

    // ---- epilogue: write split-K partials (deterministic; no atomics) ----
    float* base = &g_part[(size_t)sk * (B_DIM * N_DIM)];
    #pragma unroll
    for (int mt = 0; mt < 2; mt++) {
        const int row0 = m0 + wm * 32 + mt * 16 + (lane >> 2);
        #pragma unroll
        for (int nt = 0; nt < 8; nt++) {
            const int col = n0 + wn * 64 + nt * 8 + 2 * (lane & 3);
            *(float2*)&base[(size_t)row0 * N_DIM + col]       = make_float2(acc[mt][nt][0], acc[mt][nt][1]);
            *(float2*)&base[(size_t)(row0 + 8) * N_DIM + col] = make_float2(acc[mt][nt][2], acc[mt][nt][3]);
        }
    }
}

__global__ void StreamingConv_reduce_kernel(float* __restrict__ out)
{
    const int idx = blockIdx.x * blockDim.x + threadIdx.x;   // float2 index
    const float2* p = (const float2*)g_part;
    float2 acc = p[idx];
    #pragma unroll
    for (int i = 1; i < SPLITK; i++) {
        const float2 v = p[(size_t)i * (B_DIM * N_DIM / 2) + idx];
        acc.x += v.x; acc.y += v.y;
    }
    ((float2*)out)[idx] = acc;
}

extern "C" void kernel_launch(void* const* d_in, const int* in_sizes, int n_in,
                              void* d_out, int out_size)
{
    const float* A = (const float*)d_in[0];   // curr_input [256, 1024, 16]
    const float* W = (const float*)d_in[1];   // weight     [1024, 1024, 16]

    dim3 grid(N_DIM / TILE_N, B_DIM / TILE_M, SPLITK);   // (8, 2, 8) = 128 CTAs
    StreamingConv_gemm_kernel<<<grid, NTHREADS>>>(A, W);
    StreamingConv_reduce_kernel<<<(B_DIM * N_DIM / 2) / 256, 256>>>((float*)d_out);
}

// round 4
// speedup vs baseline: 1.2685x; 1.1526x over previous
#include <cuda_runtime.h>
#include <cuda_fp16.h>
#include <cstdint>

// D[b,o] = sum_ck A[b,ck] * W[o,ck] — GEMM M=256, N=1024, K=16384, fp32 I/O.
// fp16 operands (converted in registers), fp32 accumulate, mma.sync m16n8k16.
// 512 threads / 16 warps per CTA (4 warps per SMSP for latency hiding),
// TILE_K=32, double-buffered smem + 2-deep register staging.
#define B_DIM   256
#define N_DIM   1024
#define K_DIM   16384
#define TILE_M  128
#define TILE_N  128
#define TILE_K  32
#define SPLITK  8
#define K_PER_CTA (K_DIM / SPLITK)       // 2048
#define NITER   (K_PER_CTA / TILE_K)     // 64
#define NTHREADS 512

// Smem tile: 128 rows x 32 halfs (64 B), padded stride 80 B (16-aligned;
// 80*r mod 128 covers 8 distinct 16B banks -> conflict-free ldmatrix).
#define ROW_HB   80
#define TILE_HB  (128 * ROW_HB)           // 10240 B
#define STAGE_HB (2 * TILE_HB)            // A + B per stage
#define SMEM_BYTES (2 * STAGE_HB)         // double buffer = 40960 B

__device__ float g_part[SPLITK * B_DIM * N_DIM];

__device__ __forceinline__ uint32_t smem_u32(const void* p) {
    uint32_t a;
    asm("{ .reg .u64 t; cvta.to.shared.u64 t, %1; cvt.u32.u64 %0, t; }" : "=r"(a) : "l"(p));
    return a;
}

__device__ __forceinline__ void ldmx4(uint32_t* r, uint32_t addr) {
    asm volatile("ldmatrix.sync.aligned.m8n8.x4.shared.b16 {%0,%1,%2,%3}, [%4];"
                 : "=r"(r[0]), "=r"(r[1]), "=r"(r[2]), "=r"(r[3]) : "r"(addr));
}

__device__ __forceinline__ void mma16816(float* d, const uint32_t* a, const uint32_t* b) {
    asm volatile(
        "mma.sync.aligned.m16n8k16.row.col.f32.f16.f16.f32 "
        "{%0,%1,%2,%3}, {%4,%5,%6,%7}, {%8,%9}, {%0,%1,%2,%3};"
        : "+f"(d[0]), "+f"(d[1]), "+f"(d[2]), "+f"(d[3])
        : "r"(a[0]), "r"(a[1]), "r"(a[2]), "r"(a[3]), "r"(b[0]), "r"(b[1]));
}

__device__ __forceinline__ uint2 pack4h(float4 v) {
    __half2 lo = __floats2half2_rn(v.x, v.y);
    __half2 hi = __floats2half2_rn(v.z, v.w);
    uint2 r;
    r.x = *(uint32_t*)&lo;
    r.y = *(uint32_t*)&hi;
    return r;
}

__global__ void __launch_bounds__(NTHREADS, 1)
StreamingConv_gemm_kernel(const float* __restrict__ A, const float* __restrict__ W)
{
    __shared__ __align__(16) char smem[SMEM_BYTES];
    const uint32_t sb = smem_u32(smem);

    const int tid = threadIdx.x;
    const int lane = tid & 31;
    const int wid = tid >> 5;
    const int wm = wid >> 2;          // 0..3 -> 32-row band of M
    const int wn = wid & 3;           // 0..3 -> 32-col band of N

    const int m0 = blockIdx.y * TILE_M;
    const int n0 = blockIdx.x * TILE_N;
    const int sk = blockIdx.z;
    const size_t kbase = (size_t)sk * K_PER_CTA;

    // ---- gmem load mapping: 2 float4 for A + 2 for W per thread per iter ----
    // tile = 128 rows x 8 float4; idx = tid + 512*i -> row = idx>>3, c4 = idx&7
    const float* pa[2];
    const float* pb[2];
    uint32_t sts_off[2];
    #pragma unroll
    for (int i = 0; i < 2; i++) {
        const int idx = tid + NTHREADS * i;
        const int row = idx >> 3;     // 0..127
        const int c4  = idx & 7;      // float4 within 32-float row
        pa[i] = A + (size_t)(m0 + row) * K_DIM + kbase + c4 * 4;
        pb[i] = W + (size_t)(n0 + row) * K_DIM + kbase + c4 * 4;
        sts_off[i] = (uint32_t)(row * ROW_HB + c4 * 8);   // 4 halfs = 8 B
    }

    // ---- ldmatrix per-lane tile offsets (add ks*32 at use) ----
    uint32_t a_off[2];
    #pragma unroll
    for (int mt = 0; mt < 2; mt++)
        a_off[mt] = (uint32_t)((wm * 32 + mt * 16 + (lane & 15)) * ROW_HB + (lane >> 4) * 16);
    uint32_t b_off[2];
    #pragma unroll
    for (int p = 0; p < 2; p++)
        b_off[p] = (uint32_t)((wn * 32 + (2 * p + (lane >> 4)) * 8 + (lane & 7)) * ROW_HB
                              + ((lane >> 3) & 1) * 16);

    float acc[2][4][4];
    #pragma unroll
    for (int mt = 0; mt < 2; mt++)
        #pragma unroll
        for (int nt = 0; nt < 4; nt++)
            #pragma unroll
            for (int j = 0; j < 4; j++) acc[mt][nt][j] = 0.f;

    // ---- 2-deep register staging queue ----
    float4 qa[2][2], qb[2][2];
    #pragma unroll
    for (int d = 0; d < 2; d++) {
        const size_t ko = (size_t)d * TILE_K;
        #pragma unroll
        for (int i = 0; i < 2; i++) {
            qa[d][i] = *(const float4*)(pa[i] + ko);
            qb[d][i] = *(const float4*)(pb[i] + ko);
        }
    }
    #pragma unroll
    for (int i = 0; i < 2; i++) {
        *(uint2*)(smem + sts_off[i])           = pack4h(qa[0][i]);
        *(uint2*)(smem + TILE_HB + sts_off[i]) = pack4h(qb[0][i]);
    }
    __syncthreads();

    #pragma unroll 2
    for (int it = 0; it < NITER; ++it) {
        // LDG chunk it+2 into the slot holding chunk it (already stored last iter)
        if (it + 2 < NITER) {
            const size_t ko = (size_t)(it + 2) * TILE_K;
            const int d = it & 1;
            #pragma unroll
            for (int i = 0; i < 2; i++) {
                qa[d][i] = *(const float4*)(pa[i] + ko);
                qb[d][i] = *(const float4*)(pb[i] + ko);
            }
        }

        // compute current tile from stage it&1 (two k16 steps)
        const uint32_t baseA = sb + (uint32_t)(it & 1) * STAGE_HB;
        const uint32_t baseB = baseA + TILE_HB;
        #pragma unroll
        for (int ks = 0; ks < 2; ks++) {
            uint32_t afr[2][4], bfr[2][4];
            #pragma unroll
            for (int mt = 0; mt < 2; mt++) ldmx4(afr[mt], baseA + a_off[mt] + ks * 32);
            #pragma unroll
            for (int p = 0; p < 2; p++)  ldmx4(bfr[p], baseB + b_off[p] + ks * 32);
            #pragma unroll
            for (int mt = 0; mt < 2; mt++)
                #pragma unroll
                for (int nt = 0; nt < 4; nt++) {
                    uint32_t bb[2] = { bfr[nt >> 1][(nt & 1) * 2], bfr[nt >> 1][(nt & 1) * 2 + 1] };
                    mma16816(acc[mt][nt], afr[mt], bb);
                }
        }

        // store chunk it+1 (loaded 1 full iter ago) into the other stage
        if (it + 1 < NITER) {
            const uint32_t nxt = (uint32_t)((it + 1) & 1) * STAGE_HB;
            const int d = (it + 1) & 1;
            #pragma unroll
            for (int i = 0; i < 2; i++) {
                *(uint2*)(smem + nxt + sts_off[i])           = pack4h(qa[d][i]);
                *(uint2*)(smem + nxt + TILE_HB + sts_off[i]) = pack4h(qb[d][i]);
            }
        }
        __syncthreads();
    }

    // ---- epilogue: write split-K partials (deterministic; no atomics) ----
    float* base = &g_part[(size_t)sk * (B_DIM * N_DIM)];
    #pragma unroll
    for (int mt = 0; mt < 2; mt++) {
        const int row0 = m0 + wm * 32 + mt * 16 + (lane >> 2);
        #pragma unroll
        for (int nt = 0; nt < 4; nt++) {
            const int col = n0 + wn * 32 + nt * 8 + 2 * (lane & 3);
            *(float2*)&base[(size_t)row0 * N_DIM + col]       = make_float2(acc[mt][nt][0], acc[mt][nt][1]);
            *(float2*)&base[(size_t)(row0 + 8) * N_DIM + col] = make_float2(acc[mt][nt][2], acc[mt][nt][3]);
        }
    }
}

__global__ void StreamingConv_reduce_kernel(float* __restrict__ out)
{
    const int idx = blockIdx.x * blockDim.x + threadIdx.x;   // float4 index
    const float4* p = (const float4*)g_part;
    float4 acc = p[idx];
    #pragma unroll
    for (int i = 1; i < SPLITK; i++) {
        const float4 v = p[(size_t)i * (B_DIM * N_DIM / 4) + idx];
        acc.x += v.x; acc.y += v.y; acc.z += v.z; acc.w += v.w;
    }
    ((float4*)out)[idx] = acc;
}

extern "C" void kernel_launch(void* const* d_in, const int* in_sizes, int n_in,
                              void* d_out, int out_size)
{
    const float* A = (const float*)d_in[0];   // curr_input [256, 1024, 16]
    const float* W = (const float*)d_in[1];   // weight     [1024, 1024, 16]

    dim3 grid(N_DIM / TILE_N, B_DIM / TILE_M, SPLITK);   // (8, 2, 8) = 128 CTAs
    StreamingConv_gemm_kernel<<<grid, NTHREADS>>>(A, W);
    StreamingConv_reduce_kernel<<<(B_DIM * N_DIM / 4) / 256, 256>>>((float*)d_out);
}